// round 14
// baseline (speedup 1.0000x reference)
#include <cuda_runtime.h>
#include <cuda_bf16.h>
#include <cstdint>

#define NB 65536   // batch
#define ND 512     // embed dim
#define NP 1024    // prototypes
#define MARGIN 0.08f
#define CAP 16

// Device-global scratch (no runtime allocation allowed)
static __device__ float          g_cnorm[NP * ND];      // normalized centroids fp32
static __device__ __nv_bfloat16  g_cnorm_bf[NP * ND];   // normalized centroids bf16
static __device__ uint2          g_bfrag[128 * 32 * 32];// [colblk][kk16][lane] frag records

// Order-preserving float<->uint mapping (for atomicMax on floats)
__device__ __forceinline__ unsigned fmap(float f) {
    unsigned u = __float_as_uint(f);
    return (u & 0x80000000u) ? ~u : (u | 0x80000000u);
}
__device__ __forceinline__ float funmap(unsigned u) {
    u = (u & 0x80000000u) ? (u & 0x7fffffffu) : ~u;
    return __uint_as_float(u);
}

__device__ __forceinline__ uint32_t smem_u32(const void* p) {
    uint32_t a;
    asm("{ .reg .u64 t; cvta.to.shared.u64 t, %1; cvt.u32.u64 %0, t; }"
        : "=r"(a) : "l"(p));
    return a;
}

__device__ __forceinline__ void ldsm_x4(unsigned& r0, unsigned& r1,
                                        unsigned& r2, unsigned& r3, uint32_t addr) {
    asm volatile("ldmatrix.sync.aligned.m8n8.x4.shared.b16 {%0,%1,%2,%3}, [%4];"
                 : "=r"(r0), "=r"(r1), "=r"(r2), "=r"(r3) : "r"(addr));
}

__device__ __forceinline__ void mma16816(float* c, const unsigned* a, const unsigned* b) {
    asm volatile(
        "mma.sync.aligned.m16n8k16.row.col.f32.bf16.bf16.f32 "
        "{%0,%1,%2,%3},{%4,%5,%6,%7},{%8,%9},{%0,%1,%2,%3};\n"
        : "+f"(c[0]), "+f"(c[1]), "+f"(c[2]), "+f"(c[3])
        : "r"(a[0]), "r"(a[1]), "r"(a[2]), "r"(a[3]), "r"(b[0]), "r"(b[1]));
}

// ---------------------------------------------------------------------------
// Kernel 1: L2-normalize centroids -> fp32 + bf16 copies.
// ---------------------------------------------------------------------------
__global__ void normalize_centroids(const float* __restrict__ cent) {
    int row = blockIdx.x;
    int t   = threadIdx.x;  // 0..127
    float4 v = reinterpret_cast<const float4*>(cent + (size_t)row * ND)[t];
    float ss = v.x * v.x + v.y * v.y + v.z * v.z + v.w * v.w;
    #pragma unroll
    for (int o = 16; o > 0; o >>= 1) ss += __shfl_down_sync(0xffffffffu, ss, o);
    __shared__ float sred[4];
    if ((t & 31) == 0) sred[t >> 5] = ss;
    __syncthreads();
    float tot   = sred[0] + sred[1] + sred[2] + sred[3];
    float scale = 1.0f / fmaxf(sqrtf(tot), 1e-12f);
    float4 o4 = make_float4(v.x * scale, v.y * scale, v.z * scale, v.w * scale);
    reinterpret_cast<float4*>(g_cnorm + (size_t)row * ND)[t] = o4;
    __nv_bfloat162 p0 = __floats2bfloat162_rn(o4.x, o4.y);
    __nv_bfloat162 p1 = __floats2bfloat162_rn(o4.z, o4.w);
    uint2 pk = make_uint2(*reinterpret_cast<unsigned*>(&p0),
                          *reinterpret_cast<unsigned*>(&p1));
    reinterpret_cast<uint2*>(g_cnorm_bf)[(size_t)row * (ND / 4) + t] = pk;
}

// ---------------------------------------------------------------------------
// Kernel 1b: build fragment-native B layout (one 256B record = one warp
// B-fragment for an 8-col x 16-K subtile, lane-ordered).
// ---------------------------------------------------------------------------
__global__ void build_bfrag() {
    int r    = blockIdx.x * 8 + (threadIdx.x >> 5);  // record id 0..4095
    int lane = threadIdx.x & 31;
    int cb = r >> 5, kk = (r & 31) * 16;
    int n  = cb * 8 + (lane >> 2);
    int k0 = kk + (lane & 3) * 2;
    const unsigned* src = reinterpret_cast<const unsigned*>(g_cnorm_bf);
    unsigned x = src[(n * ND + k0) >> 1];
    unsigned y = src[(n * ND + k0 + 8) >> 1];
    g_bfrag[r * 32 + lane] = make_uint2(x, y);
}

// ---------------------------------------------------------------------------
// Kernel 2: fused GEMM-argmax. 512 threads (16 warps), CTA owns 128 rows.
//  - warp grid 4M x 4N, warp tile 32x32
//  - A resident in smem (LDSM), fragments software-pipelined 1 ahead
//  - B per-fragment coalesced LDG from g_bfrag, ring-4, prefetch 3 AHEAD
//  - epilogue barrier scoped to warpM group (4 warps) - groups decoupled
//  - one-hot zero-fill interleaved into the 8 epilogues (streaming stores)
//  - per-n-tile atomicMax rowMax + margin candidates, exact fp32 refinement
// ---------------------------------------------------------------------------
#define ASTR 520        // bf16 elems per A row (512 + 8 pad)
#define OFF_STATM 0                          // rowMaxU: 128 u32
#define OFF_CNT   512                        // rowCnt:  128 int
#define OFF_CAND  1024                       // cand:    128*CAP ushort (4096B)
#define OFF_A     5120
#define SMEM_TOTAL (OFF_A + 128 * ASTR * 2)  // 138240

__global__ __launch_bounds__(512, 1) void fused_kernel(
    const float* __restrict__ q, const float* __restrict__ cent,
    float* __restrict__ out) {
    extern __shared__ char sm[];
    uint32_t sb = smem_u32(sm);
    unsigned*       rowMaxU = reinterpret_cast<unsigned*>(sm + OFF_STATM);
    int*            rowCnt  = reinterpret_cast<int*>(sm + OFF_CNT);
    unsigned short* cand    = reinterpret_cast<unsigned short*>(sm + OFF_CAND);
    __nv_bfloat16*  sA      = reinterpret_cast<__nv_bfloat16*>(sm + OFF_A);

    const unsigned FULL = 0xffffffffu;
    int tid  = threadIdx.x;
    int lane = tid & 31, wid = tid >> 5;
    int warpM = wid & 3, warpN = wid >> 2;   // 4M x 4N grid, warp tile 32x32
    int g = lane >> 2, tc = lane & 3;
    int m0 = blockIdx.x * 128;
    unsigned mbar = warpM + 1;               // per-warpM-group barrier id

    if (tid < 128) { rowMaxU[tid] = 0u; rowCnt[tid] = 0; }

    // ---- Load resident A tile: 128 x 512 fp32 -> bf16 ----
    const float4* q4 = reinterpret_cast<const float4*>(q);
    #pragma unroll 4
    for (int e = tid; e < 128 * 128; e += 512) {
        int row = e >> 7, c = e & 127;
        float4 v = q4[(size_t)(m0 + row) * 128 + c];
        __nv_bfloat162 p0 = __floats2bfloat162_rn(v.x, v.y);
        __nv_bfloat162 p1 = __floats2bfloat162_rn(v.z, v.w);
        uint2 pk = make_uint2(*reinterpret_cast<unsigned*>(&p0),
                              *reinterpret_cast<unsigned*>(&p1));
        *reinterpret_cast<uint2*>(&sA[row * ASTR + c * 4]) = pk;
    }

    float acc[2][4][4];
    #pragma unroll
    for (int mt = 0; mt < 2; mt++)
        #pragma unroll
        for (int s = 0; s < 4; s++)
            #pragma unroll
            for (int i = 0; i < 4; i++) acc[mt][s][i] = 0.0f;

    // B fragment prefetch (3 ahead), register ring of 4
    const uint2* bbase = g_bfrag + warpN * 4096 + lane;
    unsigned b[4][4][2];   // [slot][subtile][frag]
    auto loadB = [&](int slot, int cc) {
        int off = (cc >> 5) * 16384 + (cc & 31) * 32;
        #pragma unroll
        for (int s = 0; s < 4; s++) {
            uint2 v = __ldg(bbase + off + s * 1024);
            b[slot][s][0] = v.x; b[slot][s][1] = v.y;
        }
    };

    uint32_t aAddr = sb + OFF_A +
        ((warpM * 32 + (lane & 15)) * ASTR + ((lane >> 4) << 3)) * 2;

    // A fragment prefetch (1 ahead), double buffer
    unsigned a[2][2][4];   // [buf][mt][frag]
    auto loadA = [&](int buf, int cc) {
        int kb = (cc & 31) * 16;
        #pragma unroll
        for (int mt = 0; mt < 2; mt++)
            ldsm_x4(a[buf][mt][0], a[buf][mt][1], a[buf][mt][2], a[buf][mt][3],
                    aAddr + (mt * 16 * ASTR + kb) * 2);
    };

    loadB(0, 0);
    loadB(1, 1);
    loadB(2, 2);
    __syncthreads();   // A visible, rowMax/cnt initialized
    loadA(0, 0);

    float* outHard = out + (size_t)NB * ND;
    float* outOH   = outHard + NB;

    // ---- Main loop: 256 steps = 8 n-tiles x 32 k-steps of 16 ----
    #pragma unroll 8
    for (int c = 0; c < 256; c++) {
        if (c + 3 < 256) loadB((c + 3) & 3, c + 3);
        if (c + 1 < 256) loadA((c + 1) & 1, c + 1);

        int buf = c & 1, sl = c & 3;
        #pragma unroll
        for (int mt = 0; mt < 2; mt++)
            #pragma unroll
            for (int s = 0; s < 4; s++)
                mma16816(acc[mt][s], a[buf][mt], b[sl][s]);

        if ((c & 31) == 31) {   // n-tile finished: argmax epilogue
            int n0 = (c >> 5) * 128;
            #pragma unroll
            for (int mt = 0; mt < 2; mt++) {
                float v0 = -3.4e38f, v1 = -3.4e38f;
                #pragma unroll
                for (int s = 0; s < 4; s++) {
                    v0 = fmaxf(v0, fmaxf(acc[mt][s][0], acc[mt][s][1]));
                    v1 = fmaxf(v1, fmaxf(acc[mt][s][2], acc[mt][s][3]));
                }
                v0 = fmaxf(v0, __shfl_xor_sync(FULL, v0, 1));
                v0 = fmaxf(v0, __shfl_xor_sync(FULL, v0, 2));
                v1 = fmaxf(v1, __shfl_xor_sync(FULL, v1, 1));
                v1 = fmaxf(v1, __shfl_xor_sync(FULL, v1, 2));
                if (tc == 0) {
                    int r = warpM * 32 + mt * 16 + g;
                    atomicMax(&rowMaxU[r], fmap(v0));
                    atomicMax(&rowMaxU[r + 8], fmap(v1));
                }
            }
            // Barrier over the 4 warps sharing warpM: these are ALL the
            // contributors to rows [warpM*32, +32) -> thresholds complete.
            asm volatile("bar.sync %0, %1;" :: "r"(mbar), "r"(128) : "memory");
            #pragma unroll
            for (int mt = 0; mt < 2; mt++) {
                int r0 = warpM * 32 + mt * 16 + g;
                float th0 = funmap(rowMaxU[r0]) - MARGIN;
                float th1 = funmap(rowMaxU[r0 + 8]) - MARGIN;
                #pragma unroll
                for (int s = 0; s < 4; s++) {
                    #pragma unroll
                    for (int i = 0; i < 4; i++) {
                        float v = acc[mt][s][i];
                        int   r = (i < 2) ? r0 : r0 + 8;
                        float th = (i < 2) ? th0 : th1;
                        if (v >= th) {
                            int p = atomicAdd(&rowCnt[r], 1);
                            if (p < CAP)
                                cand[r * CAP + p] = (unsigned short)
                                    (n0 + warpN * 32 + s * 8 + tc * 2 + (i & 1));
                        }
                        acc[mt][s][i] = 0.0f;
                    }
                }
            }
            // one-hot zero-fill for 16 rows (overlapped with next n-tile's
            // tensor work): rows [m0 + e*16, +16), e = tile index.
            {
                float4* ohb = reinterpret_cast<float4*>(
                    outOH + (size_t)(m0 + (c >> 5) * 16) * NP);
                float4 z = make_float4(0.f, 0.f, 0.f, 0.f);
                #pragma unroll
                for (int i = 0; i < 8; i++)
                    __stcs(ohb + tid + 512 * i, z);
            }
        }
    }
    __syncthreads();   // candidates complete; zero-fill ordered before 1.0s

    // ---- Refinement + output writes: warp w owns rows [w*8, w*8+8) ----
    const float4* c4n = reinterpret_cast<const float4*>(g_cnorm);
    const float4* ce4 = reinterpret_cast<const float4*>(cent);

    for (int rr = 0; rr < 8; rr++) {
        int r = wid * 8 + rr;
        int b2 = m0 + r;
        int cnt = rowCnt[r];
        int winner;
        if (cnt == 1) {
            winner = cand[r * CAP];
        } else {
            // exact fp32 dots; q row cached in registers
            float4 aq[4];
            const float4* qr = q4 + (size_t)b2 * 128;
            #pragma unroll
            for (int i = 0; i < 4; i++) aq[i] = qr[lane + 32 * i];
            float bv = -3.4e38f; int bi = NP;
            int lim = (cnt <= CAP) ? cnt : NP;   // overflow -> full exact scan
            for (int j = 0; j < lim; j++) {
                int col = (cnt <= CAP) ? (int)cand[r * CAP + j] : j;
                const float4* cr = c4n + (size_t)col * 128;
                float s = 0.0f;
                #pragma unroll
                for (int i = 0; i < 4; i++) {
                    float4 cc = cr[lane + 32 * i];
                    s = fmaf(aq[i].x, cc.x, fmaf(aq[i].y, cc.y,
                        fmaf(aq[i].z, cc.z, fmaf(aq[i].w, cc.w, s))));
                }
                #pragma unroll
                for (int o = 16; o > 0; o >>= 1)
                    s += __shfl_xor_sync(FULL, s, o);
                if (s > bv || (s == bv && col < bi)) { bv = s; bi = col; }
            }
            winner = bi;
        }

        // context gather (raw centroids)
        float4* ctx = reinterpret_cast<float4*>(out + (size_t)b2 * ND);
        #pragma unroll
        for (int i = 0; i < 4; i++)
            ctx[lane + 32 * i] = ce4[(size_t)winner * 128 + lane + 32 * i];
        if (lane == 0) {
            outHard[b2] = (float)winner;
            outOH[(size_t)b2 * NP + winner] = 1.0f;   // zeros already streamed
        }
    }
}

// ---------------------------------------------------------------------------
// Launch: out = [context (B*D) | hard (B) | routing (B*P)] as float32
// ---------------------------------------------------------------------------
extern "C" void kernel_launch(void* const* d_in, const int* in_sizes, int n_in,
                              void* d_out, int out_size) {
    const float* q    = (const float*)d_in[0];  // (B, D) fp32
    const float* cent = (const float*)d_in[1];  // (P, D) fp32
    float* out = (float*)d_out;

    cudaFuncSetAttribute(fused_kernel,
                         cudaFuncAttributeMaxDynamicSharedMemorySize, SMEM_TOTAL);
    normalize_centroids<<<NP, 128>>>(cent);
    build_bfrag<<<512, 256>>>();
    fused_kernel<<<NB / 128, 512, SMEM_TOTAL>>>(q, cent, out);
}